// round 3
// baseline (speedup 1.0000x reference)
#include <cuda_runtime.h>
#include <math.h>

#define NB 8
#define NC 256
#define NHW 9216
#define NHEAD 8
#define NCP 32

// ---------------- scratch (device globals; no allocation anywhere) ----------
__device__ float  g_q[NB*NC*NHW];      // 75.5 MB
__device__ float  g_k[NB*NC*NHW];
__device__ float  g_v[NB*NC*NHW];
__device__ float  g_sq[NB*NC];
__device__ float  g_sk[NB*NC];
__device__ float  g_G[NB*NHEAD*NCP*NCP];
__device__ float2 g_Chat[NB*NHEAD*NCP*NCP];
__device__ float2 g_gtab[96*96];       // g[r][t]
__device__ float2 g_T [NB*NC*NHW];     // [ch][r=hr][a]
__device__ float2 g_Tt[NB*NC*NHW];     // [ch][a][r]  (transposed)
__device__ float  g_R [NB*NC*NHW];

// ---------------- generic fp32 SGEMM: Y[b][o][s] = sum_c W[o][c] X[b][c][s] (+bias)
// M=256 (o), N=9216 (s), K=256 (c). 128x128 block tile, 8x8 per thread, K-chunk 8.
__global__ void __launch_bounds__(256) k_gemm(
    const float* __restrict__ X, const float* __restrict__ W,
    const float* __restrict__ bias, float* __restrict__ Y)
{
    __shared__ __align__(16) float Ws[8][132];
    __shared__ __align__(16) float Xs[8][132];
    const int t  = threadIdx.x;
    const int s0 = blockIdx.x * 128;
    const int o0 = blockIdx.y * 128;
    const int b  = blockIdx.z;
    const int tx = t & 15, ty = t >> 4;
    const float* Xb = X + (size_t)b * NC * NHW;

    float acc[8][8];
#pragma unroll
    for (int i = 0; i < 8; i++)
#pragma unroll
        for (int j = 0; j < 8; j++) acc[i][j] = 0.f;

    const int wi = t >> 1, wk = (t & 1) * 4;
    const int xr = t >> 5, xc = (t & 31) * 4;

    for (int kc = 0; kc < 256; kc += 8) {
        float4 w4 = *(const float4*)&W[(o0 + wi) * 256 + kc + wk];
        float4 x4 = *(const float4*)&Xb[(size_t)(kc + xr) * NHW + s0 + xc];
        __syncthreads();
        Ws[wk + 0][wi] = w4.x; Ws[wk + 1][wi] = w4.y;
        Ws[wk + 2][wi] = w4.z; Ws[wk + 3][wi] = w4.w;
        *(float4*)&Xs[xr][xc] = x4;
        __syncthreads();
#pragma unroll
        for (int kk = 0; kk < 8; kk++) {
            float a[8], bb[8];
            *(float4*)&a[0]  = *(float4*)&Ws[kk][ty * 4];
            *(float4*)&a[4]  = *(float4*)&Ws[kk][64 + ty * 4];
            *(float4*)&bb[0] = *(float4*)&Xs[kk][tx * 4];
            *(float4*)&bb[4] = *(float4*)&Xs[kk][64 + tx * 4];
#pragma unroll
            for (int i = 0; i < 8; i++)
#pragma unroll
                for (int j = 0; j < 8; j++) acc[i][j] += a[i] * bb[j];
        }
    }
#pragma unroll
    for (int i = 0; i < 8; i++) {
        int o = o0 + ((i < 4) ? ty * 4 + i : 64 + ty * 4 + i - 4);
        float bv = bias ? bias[o] : 0.f;
        float* yp = Y + (size_t)(b * NC + o) * NHW + s0;
        float4 v0 = make_float4(acc[i][0] + bv, acc[i][1] + bv, acc[i][2] + bv, acc[i][3] + bv);
        float4 v1 = make_float4(acc[i][4] + bv, acc[i][5] + bv, acc[i][6] + bv, acc[i][7] + bv);
        *(float4*)&yp[tx * 4]      = v0;
        *(float4*)&yp[64 + tx * 4] = v1;
    }
}

// ---------------- per-channel sum of squares of q and k ----------------
__global__ void __launch_bounds__(256) k_stats()
{
    const int bc = blockIdx.x;
    const float4* q4 = (const float4*)(g_q + (size_t)bc * NHW);
    const float4* k4 = (const float4*)(g_k + (size_t)bc * NHW);
    float sq = 0.f, sk = 0.f;
    for (int i = threadIdx.x; i < NHW / 4; i += 256) {
        float4 a = q4[i]; sq += a.x*a.x + a.y*a.y + a.z*a.z + a.w*a.w;
        float4 c = k4[i]; sk += c.x*c.x + c.y*c.y + c.z*c.z + c.w*c.w;
    }
#pragma unroll
    for (int o = 16; o; o >>= 1) {
        sq += __shfl_xor_sync(0xffffffff, sq, o);
        sk += __shfl_xor_sync(0xffffffff, sk, o);
    }
    __shared__ float sb[2][8];
    int w = threadIdx.x >> 5, lane = threadIdx.x & 31;
    if (lane == 0) { sb[0][w] = sq; sb[1][w] = sk; }
    __syncthreads();
    if (threadIdx.x == 0) {
        float a = 0.f, c = 0.f;
        for (int i = 0; i < 8; i++) { a += sb[0][i]; c += sb[1][i]; }
        g_sq[bc] = a; g_sk[bc] = c;
    }
}

// ---------------- zero the correlation accumulator ----------------
__global__ void k_zeroG()
{
    g_G[blockIdx.x * 256 + threadIdx.x] = 0.f;
}

// ---------------- reversed spatial correlation G[bh][c][d] (split-K, atomics)
__global__ void __launch_bounds__(256) k_corr()
{
    __shared__ float qs[32][129];
    __shared__ float ks[32][129];
    const int bh = blockIdx.x;
    const int b = bh >> 3, h = bh & 7;
    const int s0 = blockIdx.y * 128;
    const int t = threadIdx.x;
    const float* qb = g_q + (size_t)(b * NC + h * NCP) * NHW;
    const float* kb = g_k + (size_t)(b * NC + h * NCP) * NHW;
    for (int idx = t; idx < 32 * 128; idx += 256) {
        int r = idx >> 7, j = idx & 127;
        qs[r][j] = qb[(size_t)r * NHW + s0 + j];
        int s = s0 + j;
        int y = s / 96, x = s - y * 96;
        int ry = (96 - y) % 96;
        int rx = (96 - x) % 96;
        ks[r][j] = kb[(size_t)r * NHW + ry * 96 + rx];
    }
    __syncthreads();
    const int c0 = (t & 15) * 2, d0 = (t >> 4) * 2;
    float a00 = 0.f, a01 = 0.f, a10 = 0.f, a11 = 0.f;
#pragma unroll 4
    for (int j = 0; j < 128; j++) {
        float q0 = qs[c0][j], q1 = qs[c0 + 1][j];
        float k0 = ks[d0][j], k1 = ks[d0 + 1][j];
        a00 += q0 * k0; a01 += q0 * k1; a10 += q1 * k0; a11 += q1 * k1;
    }
    float* Gp = g_G + bh * 1024;
    atomicAdd(&Gp[c0 * 32 + d0],           a00);
    atomicAdd(&Gp[c0 * 32 + d0 + 1],       a01);
    atomicAdd(&Gp[(c0 + 1) * 32 + d0],     a10);
    atomicAdd(&Gp[(c0 + 1) * 32 + d0 + 1], a11);
}

// ---------------- softmax + build Chat[e][d] = (1/32) sum_c A[c][d] e^{2pi i ce/32} + (i/32) delta_e0
__global__ void __launch_bounds__(256) k_attn(const float* __restrict__ temperature)
{
    const int bh = blockIdx.x;
    const int b = bh >> 3, h = bh & 7;
    __shared__ float A[32][33];
    __shared__ float rq[32], rk[32];
    __shared__ float2 tab[32];
    const int t = threadIdx.x;
    if (t < 32) {
        rq[t] = rsqrtf(g_sq[b * NC + h * NCP + t]);
        rk[t] = rsqrtf(g_sk[b * NC + h * NCP + t]);
        float ang = 6.283185307179586f * (float)t / 32.0f;
        tab[t] = make_float2(cosf(ang), sinf(ang));
    }
    __syncthreads();
    const float ts = temperature[h];
    const int w = t >> 5, lane = t & 31;
    for (int r = w; r < 32; r += 8) {
        float L = g_G[bh * 1024 + r * 32 + lane] * rq[r] * rk[lane] * ts;
        float m = L;
#pragma unroll
        for (int o = 16; o; o >>= 1) m = fmaxf(m, __shfl_xor_sync(0xffffffff, m, o));
        float e = expf(L - m);
        float s = e;
#pragma unroll
        for (int o = 16; o; o >>= 1) s += __shfl_xor_sync(0xffffffff, s, o);
        A[r][lane] = e / s;
    }
    __syncthreads();
    for (int idx = t; idx < 1024; idx += 256) {
        int e = idx >> 5, d = idx & 31;
        float re = 0.f, im = 0.f;
#pragma unroll 8
        for (int c = 0; c < 32; c++) {
            float a = A[c][d];
            float2 tb = tab[(c * e) & 31];
            re += a * tb.x; im += a * tb.y;
        }
        re *= (1.0f / 32.0f); im *= (1.0f / 32.0f);
        if (e == 0) im += (1.0f / 32.0f);
        g_Chat[bh * 1024 + idx] = make_float2(re, im);
    }
}

// ---------------- g table (stable half-angle form) ----------------
__global__ void k_gtab()
{
    int idx = blockIdx.x * 256 + threadIdx.x;
    if (idx >= 96 * 96) return;
    int hr = idx / 96, tt = idx - hr * 96;
    float2 g;
    if (hr == 0) {
        g = make_float2(tt == 0 ? 1.f : 0.f, 0.f);
    } else {
        const float PI = 3.14159265358979323846f;
        float h1 = PI * (float)hr / 96.0f;                     // phi1/2
        float h2 = PI * (96.0f * (float)tt + (float)hr) / 9216.0f; // phi2/2
        float r = sinf(h1) / (96.0f * sinf(h2));
        float psi = h1 - h2;
        g = make_float2(r * cosf(psi), r * sinf(psi));
    }
    g_gtab[idx] = g;
}

// ---------------- v -> T: per-row circular convolution with g[r]  ----------
// grid (96 hr, 32 ch-tiles of 64); T[ch][hr][a], coalesced writes
__global__ void __launch_bounds__(256) k_vtrans()
{
    const int hr = blockIdx.x, ct = blockIdx.y;
    __shared__ float vt[64][97];
    __shared__ float2 gr[96];
    const int t = threadIdx.x;
    if (t < 96) gr[t] = g_gtab[hr * 96 + t];
    for (int idx = t; idx < 64 * 96; idx += 256) {
        int r = idx / 96, c = idx - r * 96;
        vt[r][c] = g_v[(size_t)(ct * 64 + r) * NHW + hr * 96 + c];
    }
    __syncthreads();
    const int cg = t >> 4, ag = t & 15;   // 4 channels, 6 a-values per thread
    float accr[4][6], acci[4][6];
#pragma unroll
    for (int i = 0; i < 4; i++)
#pragma unroll
        for (int j = 0; j < 6; j++) { accr[i][j] = 0.f; acci[i][j] = 0.f; }

    for (int wv = 0; wv < 96; wv++) {
        float v0 = vt[cg * 4 + 0][wv];
        float v1 = vt[cg * 4 + 1][wv];
        float v2 = vt[cg * 4 + 2][wv];
        float v3 = vt[cg * 4 + 3][wv];
#pragma unroll
        for (int j = 0; j < 6; j++) {
            int ix = ag * 6 + j - wv;
            if (ix < 0) ix += 96;
            float2 g = gr[ix];
            accr[0][j] += v0 * g.x; acci[0][j] += v0 * g.y;
            accr[1][j] += v1 * g.x; acci[1][j] += v1 * g.y;
            accr[2][j] += v2 * g.x; acci[2][j] += v2 * g.y;
            accr[3][j] += v3 * g.x; acci[3][j] += v3 * g.y;
        }
    }
#pragma unroll
    for (int i = 0; i < 4; i++)
#pragma unroll
        for (int j = 0; j < 6; j++)
            g_T[(size_t)(ct * 64 + cg * 4 + i) * NHW + hr * 96 + ag * 6 + j] =
                make_float2(accr[i][j], acci[i][j]);
}

// ---------------- per-channel 96x96 transpose: Tt[ch][a][hr] = T[ch][hr][a]
__global__ void __launch_bounds__(256) k_transpose()
{
    const int ch = blockIdx.x;
    const int tile = blockIdx.y;          // 0..8
    const int tr = (tile / 3) * 32;       // hr base
    const int tc = (tile % 3) * 32;       // a  base
    __shared__ float2 s[32][33];
    const int t = threadIdx.x;
    const size_t base = (size_t)ch * NHW;
#pragma unroll
    for (int i = 0; i < 4; i++) {
        int idx = i * 256 + t;
        int r = idx >> 5, c = idx & 31;
        s[r][c] = g_T[base + (size_t)(tr + r) * 96 + tc + c];
    }
    __syncthreads();
#pragma unroll
    for (int i = 0; i < 4; i++) {
        int idx = i * 256 + t;
        int r = idx >> 5, c = idx & 31;   // r: a-local, c: hr-local
        g_Tt[base + (size_t)(tc + r) * 96 + tr + c] = s[c][r];
    }
}

// ---------------- mix: R[bh*32+e][s] = | sum_d Chat[e][d] * Tt[bh*32+d][s] |
__global__ void __launch_bounds__(256) k_mix()
{
    const int s0 = blockIdx.x * 128;
    const int bh = blockIdx.y;
    __shared__ float2 Ch[1024];
    __shared__ float2 Ts[32][128];
    const int t = threadIdx.x;
    for (int i = t; i < 1024; i += 256) Ch[i] = g_Chat[bh * 1024 + i];
    for (int i = t; i < 4096; i += 256) {
        int d = i >> 7, j = i & 127;
        Ts[d][j] = g_Tt[(size_t)(bh * 32 + d) * NHW + s0 + j];
    }
    __syncthreads();
    const int sl = t & 63, eg = t >> 6;
    float ar0[8], ai0[8], ar1[8], ai1[8];
#pragma unroll
    for (int i = 0; i < 8; i++) { ar0[i] = ai0[i] = ar1[i] = ai1[i] = 0.f; }

    for (int d = 0; d < 32; d++) {
        float2 t0 = Ts[d][sl];
        float2 t1 = Ts[d][sl + 64];
#pragma unroll
        for (int i = 0; i < 8; i++) {
            float2 c = Ch[(eg * 8 + i) * 32 + d];
            ar0[i] += c.x * t0.x - c.y * t0.y;
            ai0[i] += c.x * t0.y + c.y * t0.x;
            ar1[i] += c.x * t1.x - c.y * t1.y;
            ai1[i] += c.x * t1.y + c.y * t1.x;
        }
    }
#pragma unroll
    for (int i = 0; i < 8; i++) {
        int row = bh * 32 + eg * 8 + i;
        g_R[(size_t)row * NHW + s0 + sl]      = sqrtf(ar0[i] * ar0[i] + ai0[i] * ai0[i]);
        g_R[(size_t)row * NHW + s0 + sl + 64] = sqrtf(ar1[i] * ar1[i] + ai1[i] * ai1[i]);
    }
}

// ---------------- launch ----------------
extern "C" void kernel_launch(void* const* d_in, const int* in_sizes, int n_in,
                              void* d_out, int out_size)
{
    const float* x    = (const float*)d_in[0];
    const float* w1   = (const float*)d_in[1];
    const float* b1   = (const float*)d_in[2];
    const float* w2   = (const float*)d_in[3];
    const float* b2   = (const float*)d_in[4];
    const float* w3   = (const float*)d_in[5];
    const float* b3   = (const float*)d_in[6];
    const float* wo   = (const float*)d_in[7];
    const float* temp = (const float*)d_in[8];
    float* out = (float*)d_out;

    float *qp = nullptr, *kp = nullptr, *vp = nullptr, *Rp = nullptr;
    cudaGetSymbolAddress((void**)&qp, g_q);
    cudaGetSymbolAddress((void**)&kp, g_k);
    cudaGetSymbolAddress((void**)&vp, g_v);
    cudaGetSymbolAddress((void**)&Rp, g_R);

    dim3 gg(72, 2, 8);                       // s-tiles, o-tiles, batch
    k_zeroG    <<<256, 256>>>();
    k_gemm     <<<gg, 256>>>(x, w1, b1, qp);
    k_gemm     <<<gg, 256>>>(x, w2, b2, kp);
    k_gemm     <<<gg, 256>>>(x, w3, b3, vp);
    k_stats    <<<2048, 256>>>();
    k_corr     <<<dim3(64, 72), 256>>>();
    k_gtab     <<<36, 256>>>();
    k_attn     <<<64, 256>>>(temp);
    k_vtrans   <<<dim3(96, 32), 256>>>();
    k_transpose<<<dim3(2048, 9), 256>>>();
    k_mix      <<<dim3(72, 64), 256>>>();
    k_gemm     <<<gg, 256>>>(Rp, wo, nullptr, out);
}